// round 11
// baseline (speedup 1.0000x reference)
#include <cuda_runtime.h>
#include <cuda_bf16.h>
#include <cstdint>

// Problem constants (fixed by the dataset)
#define NN   50000
#define EE   800000
#define HID  128
#define NH   8
#define HD   16
#define FFN  512
#define CAP  64          // max in-degree slot capacity (Poisson(16): P(>48)~3e-6 overall)
#define QKV3 384         // fused q|k|v width

// ---------------- scratch (device globals; no allocation allowed) ----------
__device__ __nv_bfloat16 g_h  [NN * HID];            // LN1 out (bf16)
__device__ __nv_bfloat16 g_qkv[(size_t)NN * QKV3];   // fused q|k|v rows (bf16)
__device__ int      g_cnt [NN];                      // in-degree (real edges)
__device__ int      g_csrc[(size_t)NN * CAP];        // padded CSR: src lists per dst
__device__ float    g_agg[NN * HID];
__device__ float    g_x1 [NN * HID];
__device__ __nv_bfloat16 g_h2 [NN * HID];            // LN2 out (bf16)
__device__ __nv_bfloat16 g_mid[(size_t)NN * FFN];    // gelu(h2@W1+b) (bf16)
// transposed bf16 weights [N, K] (+ fused qkv bias)
__device__ __nv_bfloat16 g_wqkv_t[QKV3 * HID];
__device__ float         g_bqkv  [QKV3];
__device__ __nv_bfloat16 g_wo_t[HID * HID];
__device__ __nv_bfloat16 g_w1_t[FFN * HID];
__device__ __nv_bfloat16 g_w2_t[HID * FFN];

// ---------------- helpers --------------------------------------------------
__device__ __forceinline__ float gelu_exact(float x) {
    return x * normcdff(x);          // matches jax gelu(approximate=False)
}
__device__ __forceinline__ uint32_t pack_bf2(float a, float b) {
    __nv_bfloat162 t = __floats2bfloat162_rn(a, b);
    return *reinterpret_cast<uint32_t*>(&t);
}
__device__ __forceinline__ void unpack4(uint2 d, float f[4]) {
    float2 lo = __bfloat1622float2(*reinterpret_cast<__nv_bfloat162*>(&d.x));
    float2 hi = __bfloat1622float2(*reinterpret_cast<__nv_bfloat162*>(&d.y));
    f[0] = lo.x; f[1] = lo.y; f[2] = hi.x; f[3] = hi.y;
}
__device__ __forceinline__ void cp16(uint32_t dst, const void* src, int valid) {
    asm volatile("cp.async.cg.shared.global [%0], [%1], 16, %2;"
                 :: "r"(dst), "l"(src), "r"(valid ? 16 : 0));
}

// ---------------- fused prep: weights->bf16 transposed, bias concat, cnt=0 --
__global__ void prep_kernel(const float* __restrict__ Wq, const float* __restrict__ Wk,
                            const float* __restrict__ Wv, const float* __restrict__ bq,
                            const float* __restrict__ bk, const float* __restrict__ bv,
                            const float* __restrict__ Wo, const float* __restrict__ W1,
                            const float* __restrict__ W2) {
    int i = blockIdx.x * blockDim.x + threadIdx.x;
    int stride = gridDim.x * blockDim.x;
    for (int j = i; j < QKV3 * HID; j += stride) {
        int n = j / HID, k = j % HID;
        const float* W = (n < 128) ? Wq : (n < 256) ? Wk : Wv;
        g_wqkv_t[j] = __float2bfloat16(W[k * HID + (n & 127)]);
    }
    for (int j = i; j < QKV3; j += stride)
        g_bqkv[j] = (j < 128) ? bq[j] : (j < 256) ? bk[j - 128] : bv[j - 256];
    for (int j = i; j < HID * HID; j += stride) {
        int k = j / HID, n = j % HID;
        g_wo_t[n * HID + k] = __float2bfloat16(Wo[j]);
    }
    for (int j = i; j < HID * FFN; j += stride) {
        int k = j / FFN, n = j % FFN;
        g_w1_t[n * HID + k] = __float2bfloat16(W1[j]);
    }
    for (int j = i; j < FFN * HID; j += stride) {
        int k = j / HID, n = j % HID;
        g_w2_t[n * FFN + k] = __float2bfloat16(W2[j]);
    }
    for (int j = i; j < NN; j += stride) g_cnt[j] = 0;
}

__global__ void scatter_kernel(const int* __restrict__ ei) {
    int i = blockIdx.x * blockDim.x + threadIdx.x;
    if (i >= EE) return;
    int d = ei[EE + i];
    int pos = atomicAdd(&g_cnt[d], 1);
    if (pos < CAP) g_csrc[(size_t)d * CAP + pos] = ei[i];
}

// ---------------- layernorm (warp per row, bf16 out) -----------------------
__global__ void ln_kernel(const float* __restrict__ x, const float* __restrict__ g,
                          const float* __restrict__ b, __nv_bfloat16* __restrict__ out) {
    int row = blockIdx.x * blockDim.y + threadIdx.y;
    if (row >= NN) return;
    int lane = threadIdx.x;
    float4 v = *(const float4*)(x + (size_t)row * HID + lane * 4);
    float s = v.x + v.y + v.z + v.w;
#pragma unroll
    for (int o = 16; o > 0; o >>= 1) s += __shfl_xor_sync(0xffffffffu, s, o);
    float mean = s * (1.f / HID);
    float dx = v.x - mean, dy = v.y - mean, dz = v.z - mean, dw = v.w - mean;
    float sq = dx * dx + dy * dy + dz * dz + dw * dw;
#pragma unroll
    for (int o = 16; o > 0; o >>= 1) sq += __shfl_xor_sync(0xffffffffu, sq, o);
    float rstd = rsqrtf(sq * (1.f / HID) + 1e-5f);
    float4 gg = *(const float4*)(g + lane * 4);
    float4 bb = *(const float4*)(b + lane * 4);
    uint2 o2;
    o2.x = pack_bf2(dx * rstd * gg.x + bb.x, dy * rstd * gg.y + bb.y);
    o2.y = pack_bf2(dz * rstd * gg.z + bb.z, dw * rstd * gg.w + bb.w);
    *(uint2*)(out + (size_t)row * HID + lane * 4) = o2;
}

// ---------------- per-node attention (warp per node, online softmax) --------
// Chunked gathers: batch 4 neighbors' k+v loads (MLP=8) before consuming.
__global__ void __launch_bounds__(256) node_attn_kernel() {
    int n    = (blockIdx.x * blockDim.x + threadIdx.x) >> 5;
    int lane = threadIdx.x & 31;
    if (n >= NN) return;
    int deg = g_cnt[n];
    int dd  = (deg < CAP) ? deg : CAP;
    int total = dd + 1;                       // + self loop
    const int* src_list = g_csrc + (size_t)n * CAP;

    float qv[4];
    unpack4(*(const uint2*)(g_qkv + (size_t)n * QKV3 + lane * 4), qv);

    float m = -1e30f, z = 0.f;
    float a0 = 0.f, a1 = 0.f, a2 = 0.f, a3 = 0.f;

    for (int i0 = 0; i0 < total; i0 += 4) {
        int cnt = total - i0; if (cnt > 4) cnt = 4;
        uint2 kraw[4], vraw[4];
#pragma unroll
        for (int j = 0; j < 4; j++) {
            if (j < cnt) {
                int idx = i0 + j;
                int src = (idx < dd) ? src_list[idx] : n;
                const __nv_bfloat16* base = g_qkv + (size_t)src * QKV3 + lane * 4;
                kraw[j] = *(const uint2*)(base + 128);
                vraw[j] = *(const uint2*)(base + 256);
            }
        }
#pragma unroll
        for (int j = 0; j < 4; j++) {
            if (j < cnt) {
                float kv[4];
                unpack4(kraw[j], kv);
                float p = qv[0] * kv[0] + qv[1] * kv[1] + qv[2] * kv[2] + qv[3] * kv[3];
                p += __shfl_xor_sync(0xffffffffu, p, 1);
                p += __shfl_xor_sync(0xffffffffu, p, 2);
                p *= 0.25f;                  // 1/sqrt(16)
                float mn   = fmaxf(m, p);
                float corr = __expf(m - mn);
                float e    = __expf(p - mn);
                m = mn;
                z = z * corr + e;
                float vv[4];
                unpack4(vraw[j], vv);
                a0 = a0 * corr + e * vv[0];
                a1 = a1 * corr + e * vv[1];
                a2 = a2 * corr + e * vv[2];
                a3 = a3 * corr + e * vv[3];
            }
        }
    }
    float inv = (deg > 0) ? (1.f / z) : 0.f;  // deg==0 -> zero row (reference mask)
    float4 o = make_float4(a0 * inv, a1 * inv, a2 * inv, a3 * inv);
    *(float4*)(g_agg + (size_t)n * HID + lane * 4) = o;
}

// ================= bf16 mma.sync GEMM, 2-stage cp.async pipeline ============
// C[M,N] = act(A[M,K] @ Bt[N,K]^T + bias) (+ res).
// Block 256 thr = 8 warps (4 along M x 2 along N). Tile 128x128, BK=64.
// __launch_bounds__(256, 2) forces <=128 regs so 2 CTAs/SM coexist (the round-9
// regression was 130 regs -> 1 CTA/SM).
#define TM 128
#define TN 128
#define KC 64
#define SPITCH 72
#define STAGE_ELEMS ((TM + TN) * SPITCH)          // elements per stage
#define STAGE_BYTES (STAGE_ELEMS * 2)             // 36864
#define SMEM_BYTES  (2 * STAGE_BYTES)             // 73728

__device__ __forceinline__ void ldmx4(uint32_t* r, uint32_t addr) {
    asm volatile("ldmatrix.sync.aligned.m8n8.x4.shared.b16 {%0,%1,%2,%3}, [%4];"
                 : "=r"(r[0]), "=r"(r[1]), "=r"(r[2]), "=r"(r[3]) : "r"(addr));
}
__device__ __forceinline__ void mma16816(float* c, const uint32_t* a,
                                         uint32_t b0, uint32_t b1) {
    asm volatile(
        "mma.sync.aligned.m16n8k16.row.col.f32.bf16.bf16.f32 "
        "{%0,%1,%2,%3}, {%4,%5,%6,%7}, {%8,%9}, {%0,%1,%2,%3};"
        : "+f"(c[0]), "+f"(c[1]), "+f"(c[2]), "+f"(c[3])
        : "r"(a[0]), "r"(a[1]), "r"(a[2]), "r"(a[3]), "r"(b0), "r"(b1));
}

template <int ACT, int RES, int ABF16, int CBF16>
__global__ void __launch_bounds__(256, 2)
gemm_mma(const void* __restrict__ Ap, const __nv_bfloat16* __restrict__ Bt,
         const float* __restrict__ bias, const float* __restrict__ res,
         void* __restrict__ Cp, int M, int N, int K) {
    extern __shared__ __align__(16) __nv_bfloat16 smem[];
    int tid  = threadIdx.x;
    int wid  = tid >> 5;
    int lane = tid & 31;
    int row0 = blockIdx.y * TM;
    int col0 = blockIdx.x * TN;
    int wm = (wid >> 1) * 32;
    int wn = (wid & 1) * 64;

    uint32_t sm_base = (uint32_t)__cvta_generic_to_shared(smem);

    float acc[2][8][4];
#pragma unroll
    for (int i = 0; i < 2; i++)
#pragma unroll
        for (int j = 0; j < 8; j++)
#pragma unroll
            for (int t = 0; t < 4; t++) acc[i][j][t] = 0.f;

    int a_r = (lane & 7) + ((lane >> 3) & 1) * 8;
    int a_c = (lane >> 4) * 8;
    int b_r = (lane & 7) + ((lane >> 4) << 3);
    int b_c = ((lane >> 3) & 1) * 8;

    // per-thread tile-load coords: r = seg/8, cs = (seg%8)*8
    int ld_r  = tid >> 3;
    int ld_cs = (tid & 7) << 3;

    auto load_tile = [&](int kc, int stage) {
        __nv_bfloat16* As = smem + stage * STAGE_ELEMS;
        uint32_t as_s = sm_base + stage * STAGE_BYTES;
        uint32_t bs_s = as_s + TM * SPITCH * 2;
#pragma unroll
        for (int it = 0; it < 4; it++) {
            int r = ld_r + it * 32;
            int row = row0 + r;
            if (ABF16) {
                cp16(as_s + (uint32_t)((r * SPITCH + ld_cs) * 2),
                     (const __nv_bfloat16*)Ap + (size_t)row * K + kc + ld_cs,
                     row < M);
            } else {
                uint4 val = make_uint4(0, 0, 0, 0);
                if (row < M) {
                    const float* Af = (const float*)Ap + (size_t)row * K + kc + ld_cs;
                    float4 f0 = *(const float4*)Af;
                    float4 f1 = *(const float4*)(Af + 4);
                    val.x = pack_bf2(f0.x, f0.y); val.y = pack_bf2(f0.z, f0.w);
                    val.z = pack_bf2(f1.x, f1.y); val.w = pack_bf2(f1.z, f1.w);
                }
                *(uint4*)(As + r * SPITCH + ld_cs) = val;
            }
        }
#pragma unroll
        for (int it = 0; it < 4; it++) {
            int r = ld_r + it * 32;
            cp16(bs_s + (uint32_t)((r * SPITCH + ld_cs) * 2),
                 Bt + (size_t)(col0 + r) * K + kc + ld_cs, 1);
        }
    };

    int nIter = K / KC;
    load_tile(0, 0);
    asm volatile("cp.async.commit_group;");

    for (int it = 0; it < nIter; it++) {
        int stage = it & 1;
        if (it + 1 < nIter) {
            load_tile((it + 1) * KC, stage ^ 1);
            asm volatile("cp.async.commit_group;");
            asm volatile("cp.async.wait_group 1;");
        } else {
            asm volatile("cp.async.wait_group 0;");
        }
        __syncthreads();

        uint32_t as_base = sm_base + stage * STAGE_BYTES;
        uint32_t bs_base = as_base + TM * SPITCH * 2;
#pragma unroll
        for (int kk = 0; kk < 4; kk++) {
            int k0 = kk * 16;
            uint32_t a[2][4];
#pragma unroll
            for (int mf = 0; mf < 2; mf++) {
                int r = wm + mf * 16 + a_r;
                ldmx4(a[mf], as_base + (uint32_t)((r * SPITCH + k0 + a_c) * 2));
            }
            uint32_t b[4][4];
#pragma unroll
            for (int bg = 0; bg < 4; bg++) {
                int r = wn + bg * 16 + b_r;
                ldmx4(b[bg], bs_base + (uint32_t)((r * SPITCH + k0 + b_c) * 2));
            }
#pragma unroll
            for (int mf = 0; mf < 2; mf++)
#pragma unroll
                for (int nf = 0; nf < 8; nf++) {
                    int bg = nf >> 1, lo = (nf & 1) * 2;
                    mma16816(acc[mf][nf], a[mf], b[bg][lo], b[bg][lo + 1]);
                }
        }
        __syncthreads();
    }

#pragma unroll
    for (int mf = 0; mf < 2; mf++) {
        int r_lo = row0 + wm + mf * 16 + (lane >> 2);
#pragma unroll
        for (int half = 0; half < 2; half++) {
            int row = r_lo + half * 8;
            if (row >= M) continue;
#pragma unroll
            for (int nf = 0; nf < 8; nf++) {
                int col = col0 + wn + nf * 8 + (lane & 3) * 2;
                float c0 = acc[mf][nf][half * 2 + 0];
                float c1 = acc[mf][nf][half * 2 + 1];
                c0 += bias[col];
                c1 += bias[col + 1];
                if (ACT) { c0 = gelu_exact(c0); c1 = gelu_exact(c1); }
                if (RES) {
                    const float* rp = res + (size_t)row * N + col;
                    c0 += rp[0]; c1 += rp[1];
                }
                if (CBF16) {
                    *(uint32_t*)((__nv_bfloat16*)Cp + (size_t)row * N + col) = pack_bf2(c0, c1);
                } else {
                    float2 o = make_float2(c0, c1);
                    *(float2*)((float*)Cp + (size_t)row * N + col) = o;
                }
            }
        }
    }
}

// ---------------- launch ----------------------------------------------------
extern "C" void kernel_launch(void* const* d_in, const int* in_sizes, int n_in,
                              void* d_out, int out_size) {
    const float* x   = (const float*)d_in[0];
    const int*   ei  = (const int*)  d_in[1];
    const float* Wq  = (const float*)d_in[2];
    const float* bq  = (const float*)d_in[3];
    const float* Wk  = (const float*)d_in[4];
    const float* bk  = (const float*)d_in[5];
    const float* Wv  = (const float*)d_in[6];
    const float* bv  = (const float*)d_in[7];
    const float* Wo  = (const float*)d_in[8];
    const float* bo  = (const float*)d_in[9];
    const float* g1  = (const float*)d_in[10];
    const float* b1  = (const float*)d_in[11];
    const float* g2  = (const float*)d_in[12];
    const float* b2  = (const float*)d_in[13];
    const float* W1  = (const float*)d_in[14];
    const float* bf1 = (const float*)d_in[15];
    const float* W2  = (const float*)d_in[16];
    const float* bf2 = (const float*)d_in[17];
    float* out = (float*)d_out;

    __nv_bfloat16 *h, *qkv, *h2, *mid, *wqkv_t, *wo_t, *w1_t, *w2_t;
    float *agg, *x1, *bqkv;
    cudaGetSymbolAddress((void**)&h,      g_h);
    cudaGetSymbolAddress((void**)&qkv,    g_qkv);
    cudaGetSymbolAddress((void**)&agg,    g_agg);
    cudaGetSymbolAddress((void**)&x1,     g_x1);
    cudaGetSymbolAddress((void**)&h2,     g_h2);
    cudaGetSymbolAddress((void**)&mid,    g_mid);
    cudaGetSymbolAddress((void**)&wqkv_t, g_wqkv_t);
    cudaGetSymbolAddress((void**)&bqkv,   g_bqkv);
    cudaGetSymbolAddress((void**)&wo_t,   g_wo_t);
    cudaGetSymbolAddress((void**)&w1_t,   g_w1_t);
    cudaGetSymbolAddress((void**)&w2_t,   g_w2_t);

    static int smem_set = 0;
    if (!smem_set) {
        cudaFuncSetAttribute(gemm_mma<0,0,1,1>, cudaFuncAttributeMaxDynamicSharedMemorySize, SMEM_BYTES);
        cudaFuncSetAttribute(gemm_mma<0,1,0,0>, cudaFuncAttributeMaxDynamicSharedMemorySize, SMEM_BYTES);
        cudaFuncSetAttribute(gemm_mma<1,0,1,1>, cudaFuncAttributeMaxDynamicSharedMemorySize, SMEM_BYTES);
        cudaFuncSetAttribute(gemm_mma<0,1,1,0>, cudaFuncAttributeMaxDynamicSharedMemorySize, SMEM_BYTES);
        smem_set = 1;
    }

    // fused prep (weights, biases, cnt reset) then CSR scatter
    prep_kernel<<<592, 256>>>(Wq, Wk, Wv, bq, bk, bv, Wo, W1, W2);
    scatter_kernel<<<(EE + 255) / 256, 256>>>(ei);

    // h = LN1(x) -> bf16
    {
        dim3 blk(32, 8);
        ln_kernel<<<(NN + 7) / 8, blk>>>(x, g1, b1, h);
    }

    int mtiles = (NN + TM - 1) / TM;

    // fused q|k|v projection (one GEMM, N=384, bf16 out)
    {
        dim3 grid(QKV3 / TN, mtiles);
        gemm_mma<0,0,1,1><<<grid, 256, SMEM_BYTES>>>(h, wqkv_t, bqkv, nullptr, qkv, NN, QKV3, HID);
    }

    // per-node online-softmax attention (warp per node)
    node_attn_kernel<<<(NN * 32 + 255) / 256, 256>>>();

    // x1 = x + agg @ Wo + bo
    {
        dim3 grid(HID / TN, mtiles);
        gemm_mma<0,1,0,0><<<grid, 256, SMEM_BYTES>>>(agg, wo_t, bo, x, x1, NN, HID, HID);
    }

    // h2 = LN2(x1) -> bf16
    {
        dim3 blk(32, 8);
        ln_kernel<<<(NN + 7) / 8, blk>>>(x1, g2, b2, h2);
    }

    // FFN: mid = gelu(h2 @ W1 + bf1) [bf16], out = x1 + mid @ W2 + bf2
    {
        dim3 grid1(FFN / TN, mtiles);
        gemm_mma<1,0,1,1><<<grid1, 256, SMEM_BYTES>>>(h2, w1_t, bf1, nullptr, mid, NN, FFN, HID);
        dim3 grid2(HID / TN, mtiles);
        gemm_mma<0,1,1,0><<<grid2, 256, SMEM_BYTES>>>(mid, w2_t, bf2, x1, out, NN, HID, FFN);
    }
}

// round 13
// speedup vs baseline: 1.4396x; 1.4396x over previous
#include <cuda_runtime.h>
#include <cuda_bf16.h>
#include <cstdint>

// Problem constants (fixed by the dataset)
#define NN   50000
#define EE   800000
#define HID  128
#define NH   8
#define HD   16
#define FFN  512
#define CAP  64          // max in-degree slot capacity (Poisson(16): P(>48)~3e-6 overall)
#define QKV3 384         // fused q|k|v width

// ---------------- scratch (device globals; no allocation allowed) ----------
__device__ __nv_bfloat16 g_h  [NN * HID];            // LN1 out (bf16)
// fused q|kv rows (bf16): [0,128) = q; [128,384) = interleaved k/v:
//   for lane group g in 0..31: k[4g..4g+4) at 128+8g, v[4g..4g+4) at 128+8g+4
__device__ __nv_bfloat16 g_qkv[(size_t)NN * QKV3];
__device__ int      g_cnt [NN];                      // in-degree (real edges)
__device__ int      g_csrc[(size_t)NN * CAP];        // padded CSR: src lists per dst
__device__ float    g_agg[NN * HID];
__device__ float    g_x1 [NN * HID];
__device__ __nv_bfloat16 g_h2 [NN * HID];            // LN2 out (bf16)
__device__ __nv_bfloat16 g_mid[(size_t)NN * FFN];    // gelu(h2@W1+b) (bf16)
// transposed bf16 weights [N, K] (+ fused qkv bias, column-permuted)
__device__ __nv_bfloat16 g_wqkv_t[QKV3 * HID];
__device__ float         g_bqkv  [QKV3];
__device__ __nv_bfloat16 g_wo_t[HID * HID];
__device__ __nv_bfloat16 g_w1_t[FFN * HID];
__device__ __nv_bfloat16 g_w2_t[HID * FFN];

// ---------------- helpers --------------------------------------------------
__device__ __forceinline__ float gelu_exact(float x) {
    return x * normcdff(x);          // matches jax gelu(approximate=False)
}
__device__ __forceinline__ uint32_t pack_bf2(float a, float b) {
    __nv_bfloat162 t = __floats2bfloat162_rn(a, b);
    return *reinterpret_cast<uint32_t*>(&t);
}
__device__ __forceinline__ void unpack4(uint2 d, float f[4]) {
    float2 lo = __bfloat1622float2(*reinterpret_cast<__nv_bfloat162*>(&d.x));
    float2 hi = __bfloat1622float2(*reinterpret_cast<__nv_bfloat162*>(&d.y));
    f[0] = lo.x; f[1] = lo.y; f[2] = hi.x; f[3] = hi.y;
}

// ---------------- fused prep: weights->bf16 transposed, bias concat, cnt=0 --
// Output-column permutation interleaves k|v so node_attn reads one uint4/lane.
__device__ __forceinline__ int qkv_pos(int n) {
    if (n < 128) return n;
    if (n < 256) { int d = n - 128; return 128 + ((d >> 2) << 3) + (d & 3); }
    int d = n - 256; return 128 + ((d >> 2) << 3) + 4 + (d & 3);
}

__global__ void prep_kernel(const float* __restrict__ Wq, const float* __restrict__ Wk,
                            const float* __restrict__ Wv, const float* __restrict__ bq,
                            const float* __restrict__ bk, const float* __restrict__ bv,
                            const float* __restrict__ Wo, const float* __restrict__ W1,
                            const float* __restrict__ W2) {
    int i = blockIdx.x * blockDim.x + threadIdx.x;
    int stride = gridDim.x * blockDim.x;
    for (int j = i; j < QKV3 * HID; j += stride) {
        int n = j / HID, k = j % HID;
        const float* W = (n < 128) ? Wq : (n < 256) ? Wk : Wv;
        g_wqkv_t[qkv_pos(n) * HID + k] = __float2bfloat16(W[k * HID + (n & 127)]);
    }
    for (int j = i; j < QKV3; j += stride) {
        float b = (j < 128) ? bq[j] : (j < 256) ? bk[j - 128] : bv[j - 256];
        g_bqkv[qkv_pos(j)] = b;
    }
    for (int j = i; j < HID * HID; j += stride) {
        int k = j / HID, n = j % HID;
        g_wo_t[n * HID + k] = __float2bfloat16(Wo[j]);
    }
    for (int j = i; j < HID * FFN; j += stride) {
        int k = j / FFN, n = j % FFN;
        g_w1_t[n * HID + k] = __float2bfloat16(W1[j]);
    }
    for (int j = i; j < FFN * HID; j += stride) {
        int k = j / HID, n = j % HID;
        g_w2_t[n * FFN + k] = __float2bfloat16(W2[j]);
    }
    for (int j = i; j < NN; j += stride) g_cnt[j] = 0;
}

__global__ void scatter_kernel(const int* __restrict__ ei) {
    int i = blockIdx.x * blockDim.x + threadIdx.x;
    if (i >= EE) return;
    int d = ei[EE + i];
    int pos = atomicAdd(&g_cnt[d], 1);
    if (pos < CAP) g_csrc[(size_t)d * CAP + pos] = ei[i];
}

// ---------------- layernorm (warp per row, bf16 out) -----------------------
__global__ void ln_kernel(const float* __restrict__ x, const float* __restrict__ g,
                          const float* __restrict__ b, __nv_bfloat16* __restrict__ out) {
    int row = blockIdx.x * blockDim.y + threadIdx.y;
    if (row >= NN) return;
    int lane = threadIdx.x;
    float4 v = *(const float4*)(x + (size_t)row * HID + lane * 4);
    float s = v.x + v.y + v.z + v.w;
#pragma unroll
    for (int o = 16; o > 0; o >>= 1) s += __shfl_xor_sync(0xffffffffu, s, o);
    float mean = s * (1.f / HID);
    float dx = v.x - mean, dy = v.y - mean, dz = v.z - mean, dw = v.w - mean;
    float sq = dx * dx + dy * dy + dz * dz + dw * dw;
#pragma unroll
    for (int o = 16; o > 0; o >>= 1) sq += __shfl_xor_sync(0xffffffffu, sq, o);
    float rstd = rsqrtf(sq * (1.f / HID) + 1e-5f);
    float4 gg = *(const float4*)(g + lane * 4);
    float4 bb = *(const float4*)(b + lane * 4);
    uint2 o2;
    o2.x = pack_bf2(dx * rstd * gg.x + bb.x, dy * rstd * gg.y + bb.y);
    o2.y = pack_bf2(dz * rstd * gg.z + bb.z, dw * rstd * gg.w + bb.w);
    *(uint2*)(out + (size_t)row * HID + lane * 4) = o2;
}

// ---------------- per-node attention (warp per node, online softmax) --------
// Index preload (coalesced + shfl broadcast), 4-neighbor batched uint4 k|v
// gathers (interleaved layout), registers-only accumulation, no atomics.
__global__ void __launch_bounds__(256) node_attn_kernel() {
    int n    = (blockIdx.x * blockDim.x + threadIdx.x) >> 5;
    int lane = threadIdx.x & 31;
    if (n >= NN) return;
    int deg = g_cnt[n];
    int dd  = (deg < CAP) ? deg : CAP;
    int total = dd + 1;                       // + self loop
    const int* src_list = g_csrc + (size_t)n * CAP;

    // preload first 32 src indices in one coalesced load; lanes >= dd hold n
    int reg_idx = (lane < dd) ? src_list[lane] : n;

    float qv[4];
    unpack4(*(const uint2*)(g_qkv + (size_t)n * QKV3 + lane * 4), qv);

    float m = -1e30f, z = 0.f;
    float a0 = 0.f, a1 = 0.f, a2 = 0.f, a3 = 0.f;

    for (int i0 = 0; i0 < total; i0 += 4) {
        int cnt = total - i0; if (cnt > 4) cnt = 4;
        uint4 kvraw[4];
#pragma unroll
        for (int j = 0; j < 4; j++) {
            int idx = i0 + j;                              // warp-uniform
            int src;
            if (idx < 32) src = __shfl_sync(0xffffffffu, reg_idx, idx);
            else          src = (idx < dd) ? src_list[idx] : n;   // rare tail
            if (j < cnt)
                kvraw[j] = *(const uint4*)(g_qkv + (size_t)src * QKV3 + 128 + lane * 8);
        }
#pragma unroll
        for (int j = 0; j < 4; j++) {
            if (j < cnt) {
                float kv[4], vv[4];
                unpack4(make_uint2(kvraw[j].x, kvraw[j].y), kv);
                unpack4(make_uint2(kvraw[j].z, kvraw[j].w), vv);
                float p = qv[0] * kv[0] + qv[1] * kv[1] + qv[2] * kv[2] + qv[3] * kv[3];
                p += __shfl_xor_sync(0xffffffffu, p, 1);
                p += __shfl_xor_sync(0xffffffffu, p, 2);
                p *= 0.25f;                  // 1/sqrt(16)
                float mn   = fmaxf(m, p);
                float corr = __expf(m - mn);
                float e    = __expf(p - mn);
                m = mn;
                z = z * corr + e;
                a0 = a0 * corr + e * vv[0];
                a1 = a1 * corr + e * vv[1];
                a2 = a2 * corr + e * vv[2];
                a3 = a3 * corr + e * vv[3];
            }
        }
    }
    float inv = (deg > 0) ? (1.f / z) : 0.f;  // deg==0 -> zero row (reference mask)
    float4 o = make_float4(a0 * inv, a1 * inv, a2 * inv, a3 * inv);
    *(float4*)(g_agg + (size_t)n * HID + lane * 4) = o;
}

// ================= bf16 mma.sync GEMM (round-7 version, 125 regs) ==========
// C[M,N] = act(A[M,K] @ Bt[N,K]^T + bias) (+ res).
// Block 256 thr = 8 warps (4 along M x 2 along N). Tile 128x128, BK=64.
#define TM 128
#define TN 128
#define KC 64
#define SPITCH 72

__device__ __forceinline__ void ldmx4(uint32_t* r, uint32_t addr) {
    asm volatile("ldmatrix.sync.aligned.m8n8.x4.shared.b16 {%0,%1,%2,%3}, [%4];"
                 : "=r"(r[0]), "=r"(r[1]), "=r"(r[2]), "=r"(r[3]) : "r"(addr));
}
__device__ __forceinline__ void mma16816(float* c, const uint32_t* a,
                                         uint32_t b0, uint32_t b1) {
    asm volatile(
        "mma.sync.aligned.m16n8k16.row.col.f32.bf16.bf16.f32 "
        "{%0,%1,%2,%3}, {%4,%5,%6,%7}, {%8,%9}, {%0,%1,%2,%3};"
        : "+f"(c[0]), "+f"(c[1]), "+f"(c[2]), "+f"(c[3])
        : "r"(a[0]), "r"(a[1]), "r"(a[2]), "r"(a[3]), "r"(b0), "r"(b1));
}

template <int ACT, int RES, int ABF16, int CBF16>
__global__ void __launch_bounds__(256)
gemm_mma(const void* __restrict__ Ap, const __nv_bfloat16* __restrict__ Bt,
         const float* __restrict__ bias, const float* __restrict__ res,
         void* __restrict__ Cp, int M, int N, int K) {
    __shared__ __nv_bfloat16 As[TM * SPITCH];
    __shared__ __nv_bfloat16 Bs[TN * SPITCH];
    int tid  = threadIdx.x;
    int wid  = tid >> 5;
    int lane = tid & 31;
    int row0 = blockIdx.y * TM;
    int col0 = blockIdx.x * TN;
    int wm = (wid >> 1) * 32;
    int wn = (wid & 1) * 64;

    float acc[2][8][4];
#pragma unroll
    for (int i = 0; i < 2; i++)
#pragma unroll
        for (int j = 0; j < 8; j++)
#pragma unroll
            for (int t = 0; t < 4; t++) acc[i][j][t] = 0.f;

    int a_r = (lane & 7) + ((lane >> 3) & 1) * 8;
    int a_c = (lane >> 4) * 8;
    int b_r = (lane & 7) + ((lane >> 4) << 3);
    int b_c = ((lane >> 3) & 1) * 8;

    uint32_t as_base = (uint32_t)__cvta_generic_to_shared(As);
    uint32_t bs_base = (uint32_t)__cvta_generic_to_shared(Bs);

    for (int kc = 0; kc < K; kc += KC) {
#pragma unroll
        for (int it = 0; it < 4; it++) {
            int seg = tid + it * 256;
            int r = seg >> 3, cs = (seg & 7) << 3;
            uint4 val = make_uint4(0, 0, 0, 0);
            int row = row0 + r;
            if (row < M) {
                if (ABF16) {
                    val = *(const uint4*)((const __nv_bfloat16*)Ap + (size_t)row * K + kc + cs);
                } else {
                    const float* Af = (const float*)Ap + (size_t)row * K + kc + cs;
                    float4 f0 = *(const float4*)Af;
                    float4 f1 = *(const float4*)(Af + 4);
                    val.x = pack_bf2(f0.x, f0.y); val.y = pack_bf2(f0.z, f0.w);
                    val.z = pack_bf2(f1.x, f1.y); val.w = pack_bf2(f1.z, f1.w);
                }
            }
            *(uint4*)(As + r * SPITCH + cs) = val;
        }
#pragma unroll
        for (int it = 0; it < 4; it++) {
            int seg = tid + it * 256;
            int r = seg >> 3, cs = (seg & 7) << 3;
            uint4 val = *(const uint4*)(Bt + (size_t)(col0 + r) * K + kc + cs);
            *(uint4*)(Bs + r * SPITCH + cs) = val;
        }
        __syncthreads();

#pragma unroll
        for (int kk = 0; kk < 4; kk++) {
            int k0 = kk * 16;
            uint32_t a[2][4];
#pragma unroll
            for (int mf = 0; mf < 2; mf++) {
                int r = wm + mf * 16 + a_r;
                ldmx4(a[mf], as_base + (uint32_t)((r * SPITCH + k0 + a_c) * 2));
            }
            uint32_t b[4][4];
#pragma unroll
            for (int bg = 0; bg < 4; bg++) {
                int r = wn + bg * 16 + b_r;
                ldmx4(b[bg], bs_base + (uint32_t)((r * SPITCH + k0 + b_c) * 2));
            }
#pragma unroll
            for (int mf = 0; mf < 2; mf++)
#pragma unroll
                for (int nf = 0; nf < 8; nf++) {
                    int bg = nf >> 1, lo = (nf & 1) * 2;
                    mma16816(acc[mf][nf], a[mf], b[bg][lo], b[bg][lo + 1]);
                }
        }
        __syncthreads();
    }

#pragma unroll
    for (int mf = 0; mf < 2; mf++) {
        int r_lo = row0 + wm + mf * 16 + (lane >> 2);
#pragma unroll
        for (int half = 0; half < 2; half++) {
            int row = r_lo + half * 8;
            if (row >= M) continue;
#pragma unroll
            for (int nf = 0; nf < 8; nf++) {
                int col = col0 + wn + nf * 8 + (lane & 3) * 2;
                float c0 = acc[mf][nf][half * 2 + 0];
                float c1 = acc[mf][nf][half * 2 + 1];
                c0 += bias[col];
                c1 += bias[col + 1];
                if (ACT) { c0 = gelu_exact(c0); c1 = gelu_exact(c1); }
                if (RES) {
                    const float* rp = res + (size_t)row * N + col;
                    c0 += rp[0]; c1 += rp[1];
                }
                if (CBF16) {
                    *(uint32_t*)((__nv_bfloat16*)Cp + (size_t)row * N + col) = pack_bf2(c0, c1);
                } else {
                    float2 o = make_float2(c0, c1);
                    *(float2*)((float*)Cp + (size_t)row * N + col) = o;
                }
            }
        }
    }
}

// ---------------- launch ----------------------------------------------------
extern "C" void kernel_launch(void* const* d_in, const int* in_sizes, int n_in,
                              void* d_out, int out_size) {
    const float* x   = (const float*)d_in[0];
    const int*   ei  = (const int*)  d_in[1];
    const float* Wq  = (const float*)d_in[2];
    const float* bq  = (const float*)d_in[3];
    const float* Wk  = (const float*)d_in[4];
    const float* bk  = (const float*)d_in[5];
    const float* Wv  = (const float*)d_in[6];
    const float* bv  = (const float*)d_in[7];
    const float* Wo  = (const float*)d_in[8];
    const float* bo  = (const float*)d_in[9];
    const float* g1  = (const float*)d_in[10];
    const float* b1  = (const float*)d_in[11];
    const float* g2  = (const float*)d_in[12];
    const float* b2  = (const float*)d_in[13];
    const float* W1  = (const float*)d_in[14];
    const float* bf1 = (const float*)d_in[15];
    const float* W2  = (const float*)d_in[16];
    const float* bf2 = (const float*)d_in[17];
    float* out = (float*)d_out;

    __nv_bfloat16 *h, *qkv, *h2, *mid, *wqkv_t, *wo_t, *w1_t, *w2_t;
    float *agg, *x1, *bqkv;
    cudaGetSymbolAddress((void**)&h,      g_h);
    cudaGetSymbolAddress((void**)&qkv,    g_qkv);
    cudaGetSymbolAddress((void**)&agg,    g_agg);
    cudaGetSymbolAddress((void**)&x1,     g_x1);
    cudaGetSymbolAddress((void**)&h2,     g_h2);
    cudaGetSymbolAddress((void**)&mid,    g_mid);
    cudaGetSymbolAddress((void**)&wqkv_t, g_wqkv_t);
    cudaGetSymbolAddress((void**)&bqkv,   g_bqkv);
    cudaGetSymbolAddress((void**)&wo_t,   g_wo_t);
    cudaGetSymbolAddress((void**)&w1_t,   g_w1_t);
    cudaGetSymbolAddress((void**)&w2_t,   g_w2_t);

    // fused prep (weights, biases, cnt reset) then CSR scatter
    prep_kernel<<<592, 256>>>(Wq, Wk, Wv, bq, bk, bv, Wo, W1, W2);
    scatter_kernel<<<(EE + 255) / 256, 256>>>(ei);

    // h = LN1(x) -> bf16
    {
        dim3 blk(32, 8);
        ln_kernel<<<(NN + 7) / 8, blk>>>(x, g1, b1, h);
    }

    int mtiles = (NN + TM - 1) / TM;

    // fused q|k|v projection (one GEMM, N=384, bf16 out, k|v interleaved cols)
    {
        dim3 grid(QKV3 / TN, mtiles);
        gemm_mma<0,0,1,1><<<grid, 256>>>(h, wqkv_t, bqkv, nullptr, qkv, NN, QKV3, HID);
    }

    // per-node online-softmax attention (warp per node)
    node_attn_kernel<<<(NN * 32 + 255) / 256, 256>>>();

    // x1 = x + agg @ Wo + bo
    {
        dim3 grid(HID / TN, mtiles);
        gemm_mma<0,1,0,0><<<grid, 256>>>(agg, wo_t, bo, x, x1, NN, HID, HID);
    }

    // h2 = LN2(x1) -> bf16
    {
        dim3 blk(32, 8);
        ln_kernel<<<(NN + 7) / 8, blk>>>(x1, g2, b2, h2);
    }

    // FFN: mid = gelu(h2 @ W1 + bf1) [bf16], out = x1 + mid @ W2 + bf2
    {
        dim3 grid1(FFN / TN, mtiles);
        gemm_mma<1,0,1,1><<<grid1, 256>>>(h2, w1_t, bf1, nullptr, mid, NN, FFN, HID);
        dim3 grid2(HID / TN, mtiles);
        gemm_mma<0,1,1,0><<<grid2, 256>>>(mid, w2_t, bf2, x1, out, NN, HID, FFN);
    }
}